// round 5
// baseline (speedup 1.0000x reference)
#include <cuda_runtime.h>
#include <cuda_fp16.h>
#include <cstdint>

// SimpleGNN (2-layer GCN), N=200000, E=6.4M, idx int32.
// Round 5 strategy: NO float atomics. Build CSR (deg -> scan -> counting
// sort), then pull-mode aggregation (warp per node) for both layers.
//  - layer1 aggregate-first: scatter-free sum of fp16 xs rows (1 sector/edge)
//  - per-node MLP (W1+relu+W2) unchanged
//  - layer2 pull of 8B g rows, fused bias/normalize into output.

#define MAXN 200000
#define MAXE 6400000
#define ROWP 12     // acc1 row stride (floats)
#define XH   16     // xs row stride in halves (32B = exactly one L2 sector)
#define CHUNK 1024  // scan items per block

__device__ __half d_xsh [(size_t)MAXN * XH];
__device__ float  d_xs32[(size_t)MAXN * ROWP];
__device__ float  d_acc1[(size_t)MAXN * ROWP];
__device__ float  d_dinv[MAXN];
__device__ float  d_g   [(size_t)MAXN * 2];
__device__ int    d_deg [MAXN];
__device__ int    d_rowstart[MAXN];
__device__ int    d_cursor[MAXN];
__device__ int    d_bsum[256];
__device__ int    d_csr [MAXE];

// ---------------------------------------------------------------- prologue
__global__ __launch_bounds__(256) void k_zero_deg(int n) {
    int i = blockIdx.x * blockDim.x + threadIdx.x;
    if (i < n) d_deg[i] = 0;
}

__global__ __launch_bounds__(256) void k_deg(const int* __restrict__ dst, int E) {
    int e = blockIdx.x * blockDim.x + threadIdx.x;
    if (e < E) atomicAdd(&d_deg[dst[e]], 1);
}

// dinv + pre-scaled features: fp16 row (edge gather) + fp32 row (self term).
__global__ __launch_bounds__(256) void k_scale(const float* __restrict__ x, int n) {
    int i = blockIdx.x * blockDim.x + threadIdx.x;
    if (i >= n) return;
    float dv = rsqrtf((float)(d_deg[i] + 1));
    d_dinv[i] = dv;
    const float* xi = x + (size_t)i * 10;
    float* xo = d_xs32 + (size_t)i * ROWP;
    float v[10];
#pragma unroll
    for (int k = 0; k < 10; k++) { v[k] = xi[k] * dv; xo[k] = v[k]; }
    __half2 h[5];
#pragma unroll
    for (int k = 0; k < 5; k++) h[k] = __floats2half2_rn(v[2 * k], v[2 * k + 1]);
    uint4 pk;
    pk.x = *(uint32_t*)&h[0]; pk.y = *(uint32_t*)&h[1];
    pk.z = *(uint32_t*)&h[2]; pk.w = *(uint32_t*)&h[3];
    *(uint4*)(d_xsh + (size_t)i * XH) = pk;
    *(uint32_t*)(d_xsh + (size_t)i * XH + 8) = *(uint32_t*)&h[4];
}

// ---------------------------------------------------------------- scan (3-phase)
__global__ __launch_bounds__(256) void k_s1(int n) {
    __shared__ int sm[256];
    int b = blockIdx.x, t = threadIdx.x;
    int base = b * CHUNK + t * 4;
    int s = 0;
#pragma unroll
    for (int k = 0; k < 4; k++) { int i = base + k; if (i < n) s += d_deg[i]; }
    sm[t] = s; __syncthreads();
    for (int off = 128; off > 0; off >>= 1) {
        if (t < off) sm[t] += sm[t + off];
        __syncthreads();
    }
    if (t == 0) d_bsum[b] = sm[0];
}

__global__ __launch_bounds__(256) void k_s2(int nb) {
    __shared__ int sm[256];
    int t = threadIdx.x;
    sm[t] = (t < nb) ? d_bsum[t] : 0;
    __syncthreads();
    for (int off = 1; off < 256; off <<= 1) {
        int v = (t >= off) ? sm[t - off] : 0;
        __syncthreads();
        sm[t] += v;
        __syncthreads();
    }
    d_bsum[t] = (t == 0) ? 0 : sm[t - 1];   // exclusive
}

__global__ __launch_bounds__(256) void k_s3(int n) {
    __shared__ int sm[256];
    int b = blockIdx.x, t = threadIdx.x;
    int base = b * CHUNK + t * 4;
    int v[4];
#pragma unroll
    for (int k = 0; k < 4; k++) { int i = base + k; v[k] = (i < n) ? d_deg[i] : 0; }
    int ts = v[0] + v[1] + v[2] + v[3];
    sm[t] = ts; __syncthreads();
    for (int off = 1; off < 256; off <<= 1) {          // inclusive scan of thread sums
        int a = (t >= off) ? sm[t - off] : 0;
        __syncthreads();
        sm[t] += a;
        __syncthreads();
    }
    int pos = d_bsum[b] + sm[t] - ts;                   // exclusive for this thread
#pragma unroll
    for (int k = 0; k < 4; k++) {
        int i = base + k;
        if (i < n) { d_rowstart[i] = pos; d_cursor[i] = pos; pos += v[k]; }
    }
}

// ---------------------------------------------------------------- CSR fill
__global__ __launch_bounds__(256) void k_fill(const int* __restrict__ idx, int E) {
    int e = blockIdx.x * blockDim.x + threadIdx.x;
    if (e >= E) return;
    int s = idx[e];
    int d = idx[(size_t)E + e];
    int pos = atomicAdd(&d_cursor[d], 1);
    d_csr[pos] = s;
}

// ---------------------------------------------------------------- layer-1 pull
// Warp per node: lanes gather fp16 xs rows of neighbors, fp32 accumulate,
// shfl-reduce, lane 0 writes the 10-float accumulator row. No atomics.
__global__ __launch_bounds__(256) void k_agg1(int n) {
    int w = (blockIdx.x * blockDim.x + threadIdx.x) >> 5;
    int lane = threadIdx.x & 31;
    if (w >= n) return;
    int start = d_rowstart[w];
    int cnt   = d_deg[w];
    float a[10];
#pragma unroll
    for (int k = 0; k < 10; k++) a[k] = 0.0f;
    for (int j = lane; j < cnt; j += 32) {
        int s = d_csr[start + j];
        const __half* ps = d_xsh + (size_t)s * XH;
        uint4    u  = *(const uint4*)(ps);
        uint32_t ub = *(const uint32_t*)(ps + 8);
        float2 f0 = __half22float2(*(__half2*)&u.x);
        float2 f1 = __half22float2(*(__half2*)&u.y);
        float2 f2 = __half22float2(*(__half2*)&u.z);
        float2 f3 = __half22float2(*(__half2*)&u.w);
        float2 f4 = __half22float2(*(__half2*)&ub);
        a[0] += f0.x; a[1] += f0.y; a[2] += f1.x; a[3] += f1.y;
        a[4] += f2.x; a[5] += f2.y; a[6] += f3.x; a[7] += f3.y;
        a[8] += f4.x; a[9] += f4.y;
    }
#pragma unroll
    for (int k = 0; k < 10; k++)
#pragma unroll
        for (int off = 16; off > 0; off >>= 1)
            a[k] += __shfl_down_sync(0xFFFFFFFFu, a[k], off);
    if (lane == 0) {
        float* pd = d_acc1 + (size_t)w * ROWP;
        *(float4*)(pd)     = make_float4(a[0], a[1], a[2], a[3]);
        *(float4*)(pd + 4) = make_float4(a[4], a[5], a[6], a[7]);
        *(float2*)(pd + 8) = make_float2(a[8], a[9]);
    }
}

// ---------------------------------------------------------------- node MLP
__global__ __launch_bounds__(256) void k_node(const float* __restrict__ W1,
                                              const float* __restrict__ b1,
                                              const float* __restrict__ W2, int n) {
    __shared__ float sW1[160], sb1[16], sW2[32];
    int t = threadIdx.x;
    if (t < 160) sW1[t] = W1[t];
    if (t < 16)  sb1[t] = b1[t];
    if (t < 32)  sW2[t] = W2[t];
    __syncthreads();
    int i = blockIdx.x * blockDim.x + t;
    if (i >= n) return;
    float dv = d_dinv[i];
    const float* pa = d_acc1 + (size_t)i * ROWP;
    const float* px = d_xs32 + (size_t)i * ROWP;
    float tt[10];
#pragma unroll
    for (int k = 0; k < 10; k++) tt[k] = (pa[k] + px[k]) * dv;  // (A_hat x)[i]
    float g0 = 0.0f, g1 = 0.0f;
#pragma unroll
    for (int j = 0; j < 16; j++) {
        float h = sb1[j];
#pragma unroll
        for (int k = 0; k < 10; k++) h = fmaf(tt[k], sW1[k * 16 + j], h);
        h = fmaxf(h, 0.0f);
        g0 = fmaf(h, sW2[j * 2 + 0], g0);
        g1 = fmaf(h, sW2[j * 2 + 1], g1);
    }
    d_g[2 * (size_t)i + 0] = g0 * dv;       // pre-scaled msg for layer 2
    d_g[2 * (size_t)i + 1] = g1 * dv;
}

// ---------------------------------------------------------------- layer-2 pull
// Warp per node, fuses final normalize + bias. No atomics.
__global__ __launch_bounds__(256) void k_agg2(const float* __restrict__ b2,
                                              float* __restrict__ out, int n) {
    int w = (blockIdx.x * blockDim.x + threadIdx.x) >> 5;
    int lane = threadIdx.x & 31;
    if (w >= n) return;
    int start = d_rowstart[w];
    int cnt   = d_deg[w];
    float a0 = 0.0f, a1 = 0.0f;
    for (int j = lane; j < cnt; j += 32) {
        int s = d_csr[start + j];
        float2 v = *(const float2*)(d_g + 2 * (size_t)s);
        a0 += v.x; a1 += v.y;
    }
#pragma unroll
    for (int off = 16; off > 0; off >>= 1) {
        a0 += __shfl_down_sync(0xFFFFFFFFu, a0, off);
        a1 += __shfl_down_sync(0xFFFFFFFFu, a1, off);
    }
    if (lane == 0) {
        float dv = d_dinv[w];
        float g0 = d_g[2 * (size_t)w + 0];
        float g1 = d_g[2 * (size_t)w + 1];
        out[2 * (size_t)w + 0] = dv * (a0 + g0) + __ldg(b2);
        out[2 * (size_t)w + 1] = dv * (a1 + g1) + __ldg(b2 + 1);
    }
}

extern "C" void kernel_launch(void* const* d_in, const int* in_sizes, int n_in,
                              void* d_out, int out_size) {
    const float* x  = (const float*)d_in[0];
    const int*   ei = (const int*)d_in[1];     // int32 (jax x64 disabled)
    const float* W1 = (const float*)d_in[2];
    const float* b1 = (const float*)d_in[3];
    const float* W2 = (const float*)d_in[4];
    const float* b2 = (const float*)d_in[5];
    float* out = (float*)d_out;

    int n = in_sizes[0] / 10;
    int E = in_sizes[1] / 2;

    const int TB = 256;
    int ge = (E + TB - 1) / TB;
    int gn = (n + TB - 1) / TB;
    int nb = (n + CHUNK - 1) / CHUNK;          // <= 256 for N<=262144
    int gw = (n * 32 + TB - 1) / TB;           // warp-per-node grids

    k_zero_deg<<<gn, TB>>>(n);
    k_deg     <<<ge, TB>>>(ei + E, E);         // dst row
    k_scale   <<<gn, TB>>>(x, n);
    k_s1      <<<nb, TB>>>(n);
    k_s2      <<<1,  TB>>>(nb);
    k_s3      <<<nb, TB>>>(n);
    k_fill    <<<ge, TB>>>(ei, E);
    k_agg1    <<<gw, TB>>>(n);
    k_node    <<<gn, TB>>>(W1, b1, W2, n);
    k_agg2    <<<gw, TB>>>(b2, out, n);
}

// round 6
// speedup vs baseline: 1.2153x; 1.2153x over previous
#include <cuda_runtime.h>
#include <cuda_fp16.h>
#include <cstdint>

// SimpleGNN (2-layer GCN), N=200000, E=6.4M, idx int32. Scatter pipeline
// (round-4 structure, trimmed):
//  - deg pass (int red, 4 edges/thread) -> dinv = rsqrt(deg+1)
//  - layer1 aggregate-first: A_hat(x W1) = (A_hat x) W1. Scatter fp16
//    xs = x*dinv rows (32B sector gather), fp32 v4/v2 REDs (exact accum).
//  - per-node MLP: t = dinv*(acc1+self); h1=relu(t@W1+b1); g=(h1@W2)*dinv
//  - layer2 scatter: fp16 g gather (4B, L1-resident-ish) + fp32 v2 RED.
// Scratch in __device__ globals; launches only (graph-capturable).

#define MAXN 200000
#define ROWP 12     // acc1 row stride (floats, 48B)
#define XH   16     // xs row stride in halves (32B = one L2 sector)

__device__ __half  d_xsh [(size_t)MAXN * XH];
__device__ float   d_xs32[(size_t)MAXN * ROWP];
__device__ float   d_acc1[(size_t)MAXN * ROWP];
__device__ float   d_dinv[MAXN];
__device__ float   d_g   [(size_t)MAXN * 2];   // f32 (self term, exact)
__device__ __half2 d_gh  [MAXN];               // fp16 (edge gather payload)
__device__ float   d_acc2[(size_t)MAXN * 2];
__device__ int     d_deg [MAXN];

__device__ __forceinline__ void red_add_v4(float* p, float4 v) {
    asm volatile("red.global.add.v4.f32 [%0], {%1,%2,%3,%4};"
                 :: "l"(p), "f"(v.x), "f"(v.y), "f"(v.z), "f"(v.w) : "memory");
}
__device__ __forceinline__ void red_add_v2(float* p, float2 v) {
    asm volatile("red.global.add.v2.f32 [%0], {%1,%2};"
                 :: "l"(p), "f"(v.x), "f"(v.y) : "memory");
}

__global__ __launch_bounds__(256) void k_zero_deg(int n) {
    int i = blockIdx.x * blockDim.x + threadIdx.x;
    if (i < n) d_deg[i] = 0;
}

// In-degree, 4 edges/thread (int4 index loads).
__global__ __launch_bounds__(256) void k_deg(const int* __restrict__ dst, int E) {
    int t = blockIdx.x * blockDim.x + threadIdx.x;
    int base = t * 4;
    if (base + 3 < E) {
        int4 d4 = *(const int4*)(dst + base);
        atomicAdd(&d_deg[d4.x], 1);
        atomicAdd(&d_deg[d4.y], 1);
        atomicAdd(&d_deg[d4.z], 1);
        atomicAdd(&d_deg[d4.w], 1);
    } else {
        for (int k = 0; k < 4; k++) {
            int e = base + k;
            if (e < E) atomicAdd(&d_deg[dst[e]], 1);
        }
    }
}

// dinv + pre-scaled features (fp16 row for gather, fp32 row for self term).
// Also zeros acc1/acc2 rows (replaces k_zero; runs before the scatters).
__global__ __launch_bounds__(256) void k_scale(const float* __restrict__ x, int n) {
    int i = blockIdx.x * blockDim.x + threadIdx.x;
    if (i >= n) return;
    float dv = rsqrtf((float)(d_deg[i] + 1));
    d_dinv[i] = dv;
    const float* xi = x + (size_t)i * 10;
    float* xo = d_xs32 + (size_t)i * ROWP;
    float v[10];
#pragma unroll
    for (int k = 0; k < 10; k++) { v[k] = xi[k] * dv; xo[k] = v[k]; }
    __half2 h[5];
#pragma unroll
    for (int k = 0; k < 5; k++) h[k] = __floats2half2_rn(v[2 * k], v[2 * k + 1]);
    uint4 pk;
    pk.x = *(uint32_t*)&h[0]; pk.y = *(uint32_t*)&h[1];
    pk.z = *(uint32_t*)&h[2]; pk.w = *(uint32_t*)&h[3];
    *(uint4*)(d_xsh + (size_t)i * XH) = pk;
    *(uint32_t*)(d_xsh + (size_t)i * XH + 8) = *(uint32_t*)&h[4];
    // zero accumulators
    float4 z4 = make_float4(0.f, 0.f, 0.f, 0.f);
    float* a1 = d_acc1 + (size_t)i * ROWP;
    *(float4*)(a1) = z4; *(float4*)(a1 + 4) = z4;
    *(float2*)(a1 + 8) = make_float2(0.f, 0.f);
    *(float2*)(d_acc2 + 2 * (size_t)i) = make_float2(0.f, 0.f);
}

// Layer-1 edge scatter, 2 edges/thread: gather fp16 row (16B+4B), 3 f32 REDs.
__global__ __launch_bounds__(256) void k_scat1(const int* __restrict__ idx, int E) {
    int t = blockIdx.x * blockDim.x + threadIdx.x;
    int base = t * 2;
    int s0, s1, d0, d1; int cnt;
    if (base + 1 < E) {
        int2 sp = *(const int2*)(idx + base);
        int2 dp = *(const int2*)(idx + (size_t)E + base);
        s0 = sp.x; s1 = sp.y; d0 = dp.x; d1 = dp.y; cnt = 2;
    } else if (base < E) {
        s0 = idx[base]; d0 = idx[(size_t)E + base]; s1 = d1 = 0; cnt = 1;
    } else return;
#pragma unroll
    for (int k = 0; k < 2; k++) {
        if (k >= cnt) break;
        int s = k ? s1 : s0;
        int d = k ? d1 : d0;
        const __half* ps = d_xsh + (size_t)s * XH;
        uint4    u  = *(const uint4*)(ps);
        uint32_t ub = *(const uint32_t*)(ps + 8);
        float2 f0 = __half22float2(*(__half2*)&u.x);
        float2 f1 = __half22float2(*(__half2*)&u.y);
        float2 f2 = __half22float2(*(__half2*)&u.z);
        float2 f3 = __half22float2(*(__half2*)&u.w);
        float2 f4 = __half22float2(*(__half2*)&ub);
        float* pd = d_acc1 + (size_t)d * ROWP;
        red_add_v4(pd,     make_float4(f0.x, f0.y, f1.x, f1.y));
        red_add_v4(pd + 4, make_float4(f2.x, f2.y, f3.x, f3.y));
        red_add_v2(pd + 8, make_float2(f4.x, f4.y));
    }
}

// Per-node MLP; writes g in both f32 (self term) and fp16 (gather payload).
__global__ __launch_bounds__(256) void k_node(const float* __restrict__ W1,
                                              const float* __restrict__ b1,
                                              const float* __restrict__ W2, int n) {
    __shared__ float sW1[160], sb1[16], sW2[32];
    int t = threadIdx.x;
    if (t < 160) sW1[t] = W1[t];
    if (t < 16)  sb1[t] = b1[t];
    if (t < 32)  sW2[t] = W2[t];
    __syncthreads();
    int i = blockIdx.x * blockDim.x + t;
    if (i >= n) return;
    float dv = d_dinv[i];
    const float* pa = d_acc1 + (size_t)i * ROWP;
    const float* px = d_xs32 + (size_t)i * ROWP;
    float tt[10];
#pragma unroll
    for (int k = 0; k < 10; k++) tt[k] = (pa[k] + px[k]) * dv;  // (A_hat x)[i]
    float g0 = 0.0f, g1 = 0.0f;
#pragma unroll
    for (int j = 0; j < 16; j++) {
        float h = sb1[j];
#pragma unroll
        for (int k = 0; k < 10; k++) h = fmaf(tt[k], sW1[k * 16 + j], h);
        h = fmaxf(h, 0.0f);
        g0 = fmaf(h, sW2[j * 2 + 0], g0);
        g1 = fmaf(h, sW2[j * 2 + 1], g1);
    }
    g0 *= dv; g1 *= dv;                      // pre-scaled msg for layer 2
    d_g[2 * (size_t)i + 0] = g0;
    d_g[2 * (size_t)i + 1] = g1;
    d_gh[i] = __floats2half2_rn(g0, g1);
}

// Layer-2 edge scatter, 4 edges/thread: fp16 4B gather + f32 v2 RED.
__global__ __launch_bounds__(256) void k_scat2(const int* __restrict__ idx, int E) {
    int t = blockIdx.x * blockDim.x + threadIdx.x;
    int base = t * 4;
    if (base + 3 < E) {
        int4 sp = *(const int4*)(idx + base);
        int4 dp = *(const int4*)(idx + (size_t)E + base);
        float2 v0 = __half22float2(d_gh[sp.x]);
        float2 v1 = __half22float2(d_gh[sp.y]);
        float2 v2 = __half22float2(d_gh[sp.z]);
        float2 v3 = __half22float2(d_gh[sp.w]);
        red_add_v2(d_acc2 + 2 * (size_t)dp.x, v0);
        red_add_v2(d_acc2 + 2 * (size_t)dp.y, v1);
        red_add_v2(d_acc2 + 2 * (size_t)dp.z, v2);
        red_add_v2(d_acc2 + 2 * (size_t)dp.w, v3);
    } else {
        for (int k = 0; k < 4; k++) {
            int e = base + k;
            if (e < E) {
                int s = idx[e];
                int d = idx[(size_t)E + e];
                red_add_v2(d_acc2 + 2 * (size_t)d, __half22float2(d_gh[s]));
            }
        }
    }
}

// Final: out = dinv*(acc2 + self_f32) + b2
__global__ __launch_bounds__(256) void k_out(const float* __restrict__ b2,
                                             float* __restrict__ out, int n) {
    int i = blockIdx.x * blockDim.x + threadIdx.x;
    if (i >= n) return;
    float dv = d_dinv[i];
    float2 a = *(const float2*)(d_acc2 + 2 * (size_t)i);
    float2 g = *(const float2*)(d_g + 2 * (size_t)i);
    out[2 * (size_t)i + 0] = dv * (a.x + g.x) + __ldg(b2);
    out[2 * (size_t)i + 1] = dv * (a.y + g.y) + __ldg(b2 + 1);
}

extern "C" void kernel_launch(void* const* d_in, const int* in_sizes, int n_in,
                              void* d_out, int out_size) {
    const float* x  = (const float*)d_in[0];
    const int*   ei = (const int*)d_in[1];     // int32 (jax x64 disabled)
    const float* W1 = (const float*)d_in[2];
    const float* b1 = (const float*)d_in[3];
    const float* W2 = (const float*)d_in[4];
    const float* b2 = (const float*)d_in[5];
    float* out = (float*)d_out;

    int n = in_sizes[0] / 10;
    int E = in_sizes[1] / 2;

    const int TB = 256;
    int gn  = (n + TB - 1) / TB;
    int ge2 = ((E + 1) / 2 + TB - 1) / TB;
    int ge4 = ((E + 3) / 4 + TB - 1) / TB;

    k_zero_deg<<<gn,  TB>>>(n);
    k_deg     <<<ge4, TB>>>(ei + E, E);     // dst row
    k_scale   <<<gn,  TB>>>(x, n);
    k_scat1   <<<ge2, TB>>>(ei, E);
    k_node    <<<gn,  TB>>>(W1, b1, W2, n);
    k_scat2   <<<ge4, TB>>>(ei, E);
    k_out     <<<gn,  TB>>>(b2, out, n);
}